// round 1
// baseline (speedup 1.0000x reference)
#include <cuda_runtime.h>

// Conv 3x3, stride 1, pad 1, NCHW fp32.
// x: [32, 128, 56, 56], w: [256, 128, 3, 3], bias: [256] -> out: [32, 256, 56, 56]
// Implicit GEMM: M = 256 (out channels), N = 100352 (pixels), K = 1152 (C*9).

#define N_IMG 32
#define C_IN 128
#define HW 56
#define PIX_PER_IMG (HW * HW)            // 3136
#define K_OUT 256
#define KDIM (C_IN * 9)                  // 1152
#define NPIX (N_IMG * PIX_PER_IMG)       // 100352

#define BM 128
#define BN 128
#define BK 8
#define NTHREADS 256
#define KITERS (KDIM / BK)               // 144

__device__ __forceinline__ void gather_b(const float* __restrict__ xN,
                                         int qh, int qw, int k,
                                         float b[4]) {
    // k -> (c, r, s)
    const int c  = k / 9;
    const int rs = k - c * 9;
    const int r  = rs / 3;
    const int s  = rs - r * 3;
    const int ih = qh + r - 1;
    const bool rowOK = ((unsigned)ih < (unsigned)HW);
    const float* row = xN + c * PIX_PER_IMG + ih * HW;
#pragma unroll
    for (int j = 0; j < 4; ++j) {
        const int iw = qw + j + s - 1;
        b[j] = (rowOK && (unsigned)iw < (unsigned)HW) ? __ldg(row + iw) : 0.0f;
    }
}

__global__ __launch_bounds__(NTHREADS, 2)
void conv3x3_igemm_kernel(const float* __restrict__ x,
                          const float* __restrict__ wgt,
                          const float* __restrict__ bias,
                          float* __restrict__ out) {
    __shared__ float As[2][BK][BM];
    __shared__ float Bs[2][BK][BN];

    const int tid     = threadIdx.x;
    const int pixBase = blockIdx.x * BN;
    const int mBase   = blockIdx.y * BM;

    // ---- B loader: warp (tid>>5) owns k-row bKK; each lane owns 4 consecutive pixels.
    // pixBase is a multiple of 128 and 3136 % 4 == 0, 56 % 4 == 0 -> a 4-pixel quad
    // never crosses an image or an H-row boundary.
    const int bKK   = tid >> 5;          // 0..7
    const int bLane = tid & 31;          // 0..31
    const int pQuad = pixBase + bLane * 4;
    const int qn    = pQuad / PIX_PER_IMG;
    const int qrem  = pQuad - qn * PIX_PER_IMG;
    const int qh    = qrem / HW;
    const int qw    = qrem - qh * HW;
    const float* xN = x + qn * (C_IN * PIX_PER_IMG);

    // ---- A loader: thread loads one float4 of the weight row (K-major chunk).
    const int mA = tid >> 1;             // 0..127
    const int kA = (tid & 1) * 4;        // 0 or 4
    const float* wRow = wgt + (mBase + mA) * KDIM + kA;

    // ---- compute mapping: 16x16 threads, each computes 8 (M) x 8 (pixels)
    const int tm = tid >> 4;             // 0..15
    const int tn = tid & 15;             // 0..15

    float acc[8][8];
#pragma unroll
    for (int i = 0; i < 8; ++i)
#pragma unroll
        for (int j = 0; j < 8; ++j)
            acc[i][j] = 0.0f;

    // ---- prologue: fill stage 0 (k0 = 0)
    {
        const float4 a0 = *reinterpret_cast<const float4*>(wRow);
        float b0[4];
        gather_b(xN, qh, qw, bKK, b0);
        As[0][kA + 0][mA] = a0.x;
        As[0][kA + 1][mA] = a0.y;
        As[0][kA + 2][mA] = a0.z;
        As[0][kA + 3][mA] = a0.w;
#pragma unroll
        for (int j = 0; j < 4; ++j)
            Bs[0][bKK][bLane * 4 + j] = b0[j];
    }
    __syncthreads();

    // ---- main loop, register-staged double buffering
    for (int t = 0; t < KITERS; ++t) {
        const int st = t & 1;

        float4 aN;
        float  bN[4];
        const bool has = (t + 1) < KITERS;
        if (has) {
            const int k0 = (t + 1) * BK;
            aN = *reinterpret_cast<const float4*>(wRow + k0);
            gather_b(xN, qh, qw, k0 + bKK, bN);
        }

        // compute on stage st
#pragma unroll
        for (int kk = 0; kk < BK; ++kk) {
            float a[8], b[8];
            *reinterpret_cast<float4*>(&a[0]) =
                *reinterpret_cast<const float4*>(&As[st][kk][tm * 8]);
            *reinterpret_cast<float4*>(&a[4]) =
                *reinterpret_cast<const float4*>(&As[st][kk][tm * 8 + 4]);
            *reinterpret_cast<float4*>(&b[0]) =
                *reinterpret_cast<const float4*>(&Bs[st][kk][tn * 8]);
            *reinterpret_cast<float4*>(&b[4]) =
                *reinterpret_cast<const float4*>(&Bs[st][kk][tn * 8 + 4]);
#pragma unroll
            for (int i = 0; i < 8; ++i)
#pragma unroll
                for (int j = 0; j < 8; ++j)
                    acc[i][j] = fmaf(a[i], b[j], acc[i][j]);
        }

        if (has) {
            const int st2 = st ^ 1;
            As[st2][kA + 0][mA] = aN.x;
            As[st2][kA + 1][mA] = aN.y;
            As[st2][kA + 2][mA] = aN.z;
            As[st2][kA + 3][mA] = aN.w;
#pragma unroll
            for (int j = 0; j < 4; ++j)
                Bs[st2][bKK][bLane * 4 + j] = bN[j];
        }
        __syncthreads();
    }

    // ---- epilogue: 8-pixel groups are contiguous within an image (3136 % 8 == 0),
    // so stores vectorize as float4.
    const int pGrp = pixBase + tn * 8;
    const int on   = pGrp / PIX_PER_IMG;
    const int ohw  = pGrp - on * PIX_PER_IMG;
    float* outBase = out + (size_t)on * (K_OUT * PIX_PER_IMG) + ohw;

#pragma unroll
    for (int i = 0; i < 8; ++i) {
        const int kout = mBase + tm * 8 + i;
        const float bv = __ldg(&bias[kout]);
        float* o = outBase + (size_t)kout * PIX_PER_IMG;
        float4 v0, v1;
        v0.x = acc[i][0] + bv; v0.y = acc[i][1] + bv;
        v0.z = acc[i][2] + bv; v0.w = acc[i][3] + bv;
        v1.x = acc[i][4] + bv; v1.y = acc[i][5] + bv;
        v1.z = acc[i][6] + bv; v1.w = acc[i][7] + bv;
        *reinterpret_cast<float4*>(o)     = v0;
        *reinterpret_cast<float4*>(o + 4) = v1;
    }
}

extern "C" void kernel_launch(void* const* d_in, const int* in_sizes, int n_in,
                              void* d_out, int out_size) {
    const float* x    = (const float*)d_in[0];
    const float* wgt  = (const float*)d_in[1];
    const float* bias = (const float*)d_in[2];
    float* out        = (float*)d_out;

    dim3 grid(NPIX / BN, K_OUT / BM);   // (784, 2)
    conv3x3_igemm_kernel<<<grid, NTHREADS>>>(x, wgt, bias, out);
}

// round 2
// speedup vs baseline: 1.1199x; 1.1199x over previous
#include <cuda_runtime.h>

// Conv 3x3, stride 1, pad 1, NCHW fp32.
// x: [32, 128, 56, 56], w: [256, 128, 3, 3], bias: [256] -> out: [32, 256, 56, 56]
// Implicit GEMM: M = 256 (out channels), N = 100352 (pixels), K = 1152 (C*3*3).
// Round 2: inner product uses packed fma.rn.f32x2 (Blackwell FFMA2) -> 2x fp32 rate.

#define N_IMG 32
#define C_IN 128
#define HW 56
#define PIX_PER_IMG (HW * HW)            // 3136
#define K_OUT 256
#define KDIM (C_IN * 9)                  // 1152
#define NPIX (N_IMG * PIX_PER_IMG)       // 100352

#define BM 128
#define BN 128
#define BK 8
#define NTHREADS 256
#define KITERS (KDIM / BK)               // 144

typedef unsigned long long u64;

__device__ __forceinline__ u64 pack2_dup(float x) {
    u64 r;
    asm("mov.b64 %0, {%1, %1};" : "=l"(r) : "f"(x));
    return r;
}

__device__ __forceinline__ void ffma2(u64& d, u64 a, u64 b) {
    asm("fma.rn.f32x2 %0, %1, %2, %0;" : "+l"(d) : "l"(a), "l"(b));
}

__device__ __forceinline__ void unpack2(u64 v, float& lo, float& hi) {
    asm("mov.b64 {%0, %1}, %2;" : "=f"(lo), "=f"(hi) : "l"(v));
}

__device__ __forceinline__ void gather_b(const float* __restrict__ xN,
                                         int qh, int qw, int k,
                                         float b[4]) {
    // k -> (c, r, s)
    const int c  = k / 9;
    const int rs = k - c * 9;
    const int r  = rs / 3;
    const int s  = rs - r * 3;
    const int ih = qh + r - 1;
    const bool rowOK = ((unsigned)ih < (unsigned)HW);
    const float* row = xN + c * PIX_PER_IMG + ih * HW;
#pragma unroll
    for (int j = 0; j < 4; ++j) {
        const int iw = qw + j + s - 1;
        b[j] = (rowOK && (unsigned)iw < (unsigned)HW) ? __ldg(row + iw) : 0.0f;
    }
}

__global__ __launch_bounds__(NTHREADS, 2)
void conv3x3_igemm_f32x2_kernel(const float* __restrict__ x,
                                const float* __restrict__ wgt,
                                const float* __restrict__ bias,
                                float* __restrict__ out) {
    __shared__ float As[2][BK][BM];
    __shared__ float Bs[2][BK][BN];

    const int tid     = threadIdx.x;
    const int pixBase = blockIdx.x * BN;
    const int mBase   = blockIdx.y * BM;

    // ---- B loader: warp (tid>>5) owns k-row bKK; each lane owns 4 consecutive pixels.
    const int bKK   = tid >> 5;          // 0..7
    const int bLane = tid & 31;          // 0..31
    const int pQuad = pixBase + bLane * 4;
    const int qn    = pQuad / PIX_PER_IMG;
    const int qrem  = pQuad - qn * PIX_PER_IMG;
    const int qh    = qrem / HW;
    const int qw    = qrem - qh * HW;
    const float* xN = x + qn * (C_IN * PIX_PER_IMG);

    // ---- A loader: thread loads one float4 of the weight row (K-major chunk).
    const int mA = tid >> 1;             // 0..127
    const int kA = (tid & 1) * 4;        // 0 or 4
    const float* wRow = wgt + (mBase + mA) * KDIM + kA;

    // ---- compute mapping: 16x16 threads, each computes 8 (M) x 8 (pixels)
    const int tm = tid >> 4;             // 0..15
    const int tn = tid & 15;             // 0..15

    // accumulators: 8 M-rows x 4 pixel-pairs, packed f32x2
    u64 acc2[8][4];
#pragma unroll
    for (int i = 0; i < 8; ++i)
#pragma unroll
        for (int jp = 0; jp < 4; ++jp)
            acc2[i][jp] = 0ULL;

    // ---- prologue: fill stage 0
    {
        const float4 a0 = *reinterpret_cast<const float4*>(wRow);
        float b0[4];
        gather_b(xN, qh, qw, bKK, b0);
        As[0][kA + 0][mA] = a0.x;
        As[0][kA + 1][mA] = a0.y;
        As[0][kA + 2][mA] = a0.z;
        As[0][kA + 3][mA] = a0.w;
#pragma unroll
        for (int j = 0; j < 4; ++j)
            Bs[0][bKK][bLane * 4 + j] = b0[j];
    }
    __syncthreads();

    // ---- main loop, register-staged double buffering
    for (int t = 0; t < KITERS; ++t) {
        const int st = t & 1;

        float4 aN;
        float  bN[4];
        const bool has = (t + 1) < KITERS;
        if (has) {
            const int k0 = (t + 1) * BK;
            aN = *reinterpret_cast<const float4*>(wRow + k0);
            gather_b(xN, qh, qw, k0 + bKK, bN);
        }

        // compute on stage st
#pragma unroll
        for (int kk = 0; kk < BK; ++kk) {
            float a[8];
            *reinterpret_cast<float4*>(&a[0]) =
                *reinterpret_cast<const float4*>(&As[st][kk][tm * 8]);
            *reinterpret_cast<float4*>(&a[4]) =
                *reinterpret_cast<const float4*>(&As[st][kk][tm * 8 + 4]);

            // b as 4 packed f32x2 straight from LDS.128 register pairs
            ulonglong2 bl0 = *reinterpret_cast<const ulonglong2*>(&Bs[st][kk][tn * 8]);
            ulonglong2 bl1 = *reinterpret_cast<const ulonglong2*>(&Bs[st][kk][tn * 8 + 4]);
            u64 b2[4];
            b2[0] = bl0.x; b2[1] = bl0.y; b2[2] = bl1.x; b2[3] = bl1.y;

#pragma unroll
            for (int i = 0; i < 8; ++i) {
                const u64 aa = pack2_dup(a[i]);
#pragma unroll
                for (int jp = 0; jp < 4; ++jp)
                    ffma2(acc2[i][jp], aa, b2[jp]);
            }
        }

        if (has) {
            const int st2 = st ^ 1;
            As[st2][kA + 0][mA] = aN.x;
            As[st2][kA + 1][mA] = aN.y;
            As[st2][kA + 2][mA] = aN.z;
            As[st2][kA + 3][mA] = aN.w;
#pragma unroll
            for (int j = 0; j < 4; ++j)
                Bs[st2][bKK][bLane * 4 + j] = bN[j];
        }
        __syncthreads();
    }

    // ---- epilogue: 8-pixel groups contiguous within image (3136 % 8 == 0) -> float4 stores
    const int pGrp = pixBase + tn * 8;
    const int on   = pGrp / PIX_PER_IMG;
    const int ohw  = pGrp - on * PIX_PER_IMG;
    float* outBase = out + (size_t)on * (K_OUT * PIX_PER_IMG) + ohw;

#pragma unroll
    for (int i = 0; i < 8; ++i) {
        const int kout = mBase + tm * 8 + i;
        const float bv = __ldg(&bias[kout]);
        float* o = outBase + (size_t)kout * PIX_PER_IMG;
        float v[8];
#pragma unroll
        for (int jp = 0; jp < 4; ++jp)
            unpack2(acc2[i][jp], v[jp * 2], v[jp * 2 + 1]);
        float4 v0, v1;
        v0.x = v[0] + bv; v0.y = v[1] + bv; v0.z = v[2] + bv; v0.w = v[3] + bv;
        v1.x = v[4] + bv; v1.y = v[5] + bv; v1.z = v[6] + bv; v1.w = v[7] + bv;
        *reinterpret_cast<float4*>(o)     = v0;
        *reinterpret_cast<float4*>(o + 4) = v1;
    }
}

extern "C" void kernel_launch(void* const* d_in, const int* in_sizes, int n_in,
                              void* d_out, int out_size) {
    const float* x    = (const float*)d_in[0];
    const float* wgt  = (const float*)d_in[1];
    const float* bias = (const float*)d_in[2];
    float* out        = (float*)d_out;

    dim3 grid(NPIX / BN, K_OUT / BM);   // (784, 2)
    conv3x3_igemm_f32x2_kernel<<<grid, NTHREADS>>>(x, wgt, bias, out);
}

// round 4
// speedup vs baseline: 3.1342x; 2.7986x over previous
#include <cuda_runtime.h>
#include <cuda_bf16.h>
#include <stdint.h>

// Conv 3x3 s1 p1, NCHW fp32: x[32,128,56,56] * w[256,128,3,3] + bias -> out[32,256,56,56]
// bf16-split implicit GEMM on mma.sync.m16n8k16 (HMMA). 3 MMAs (hh, hl, lh) emulate fp32.

#define N_IMG 32
#define C_IN  128
#define HW    56
#define PIX   3136              // 56*56
#define K_OUT 256
#define NPIX  100352            // 32*3136
#define BM    128               // out-channels per CTA
#define BN    128               // pixels per CTA
#define NKT   18                // K steps: 9 (r,s) x 2 c-halves of 64
#define NTHREADS 256

// ---------------- scratch (device globals; no allocs allowed) ----------------
__device__ __align__(16) __nv_bfloat16 g_xt_hi[(size_t)NPIX * C_IN];   // NHWC hi
__device__ __align__(16) __nv_bfloat16 g_xt_lo[(size_t)NPIX * C_IN];   // NHWC lo
__device__ __align__(16) __nv_bfloat16 g_w_hi[NKT * 256 * 64];         // [kt][m][c64]
__device__ __align__(16) __nv_bfloat16 g_w_lo[NKT * 256 * 64];

// ---------------- helpers ----------------
__device__ __forceinline__ uint32_t smem_u32(const void* p) {
    uint32_t a;
    asm("{ .reg .u64 t; cvta.to.shared.u64 t, %1; cvt.u32.u64 %0, t; }" : "=r"(a) : "l"(p));
    return a;
}
__device__ __forceinline__ uint32_t sw128(uint32_t off) { return off ^ ((off >> 3) & 0x70); }

__device__ __forceinline__ void cp16(uint32_t dst, const void* src, int src_sz) {
    asm volatile("cp.async.cg.shared.global [%0], [%1], 16, %2;"
                 :: "r"(dst), "l"(src), "r"(src_sz) : "memory");
}
__device__ __forceinline__ void ldsm4(uint32_t* r, uint32_t a) {
    asm volatile("ldmatrix.sync.aligned.m8n8.x4.shared.b16 {%0,%1,%2,%3}, [%4];"
                 : "=r"(r[0]), "=r"(r[1]), "=r"(r[2]), "=r"(r[3]) : "r"(a));
}
__device__ __forceinline__ void mma_bf16(float* c, const uint32_t* a, const uint32_t* b) {
    asm volatile(
        "mma.sync.aligned.m16n8k16.row.col.f32.bf16.bf16.f32 "
        "{%0,%1,%2,%3}, {%4,%5,%6,%7}, {%8,%9}, {%0,%1,%2,%3};"
        : "+f"(c[0]), "+f"(c[1]), "+f"(c[2]), "+f"(c[3])
        : "r"(a[0]), "r"(a[1]), "r"(a[2]), "r"(a[3]), "r"(b[0]), "r"(b[1]));
}

// ---------------- smem layout: 3-stage ring, 64 KB per stage ----------------
// stage: A[part0] 16K | A[part1] 16K | B[part0] 16K | B[part1] 16K
#define STAGE_BYTES 65536
#define A_OFF(st, p) ((st) * STAGE_BYTES + (p) * 16384)
#define B_OFF(st, p) ((st) * STAGE_BYTES + 32768 + (p) * 16384)
#define SMEM_TOTAL (3 * STAGE_BYTES)

// ---------------- prep kernels ----------------
__global__ void wprep_kernel(const float* __restrict__ w) {
    int idx = blockIdx.x * 256 + threadIdx.x;     // < 256*1152
    int m = idx / 1152;
    int k = idx - m * 1152;
    int c = k / 9;
    int rs = k - c * 9;
    float v = w[idx];
    __nv_bfloat16 hi = __float2bfloat16(v);
    __nv_bfloat16 lo = __float2bfloat16(v - __bfloat162float(hi));
    int kt = rs * 2 + (c >> 6);
    int dst = (kt * 256 + m) * 64 + (c & 63);
    g_w_hi[dst] = hi;
    g_w_lo[dst] = lo;
}

__global__ void xprep_kernel(const float* __restrict__ x) {
    __shared__ float t[32][33];
    const int n  = blockIdx.z;
    const int c0 = blockIdx.y * 32;
    const int p0 = blockIdx.x * 32;
    const int tx = threadIdx.x, ty = threadIdx.y;   // 32 x 8
    const float* src = x + ((size_t)n * C_IN + c0) * PIX + p0;
#pragma unroll
    for (int i = 0; i < 4; ++i) {
        int c = ty + i * 8;
        t[c][tx] = src[(size_t)c * PIX + tx];
    }
    __syncthreads();
#pragma unroll
    for (int i = 0; i < 4; ++i) {
        int pr = ty + i * 8;
        float v = t[tx][pr];
        __nv_bfloat16 hi = __float2bfloat16(v);
        __nv_bfloat16 lo = __float2bfloat16(v - __bfloat162float(hi));
        size_t dst = ((size_t)n * PIX + p0 + pr) * C_IN + c0 + tx;
        g_xt_hi[dst] = hi;
        g_xt_lo[dst] = lo;
    }
}

// ---------------- main conv kernel ----------------
__global__ __launch_bounds__(NTHREADS, 1)
void conv_mma_kernel(const float* __restrict__ bias, float* __restrict__ out) {
    extern __shared__ char smem[];
    const uint32_t sbase = smem_u32(smem);
    const int tid = threadIdx.x;
    const int wid = tid >> 5;
    const int l   = tid & 31;
    const int pixBase = blockIdx.x * BN;
    const int mBase   = blockIdx.y * BM;
    const int wy = wid & 1;            // M half (64 rows)
    const int wx = wid >> 1;           // N quarter (32 pixels)

    // ---- per-thread B-row geometry (fixed across ksteps) ----
    const int brow = tid >> 1;          // 0..127 (pixel row of B tile)
    const int bhr  = tid & 1;           // half-row (64B each)
    const int p    = pixBase + brow;
    const int bn   = p / PIX;
    const int brem = p - bn * PIX;
    const int bh   = brem / HW;
    const int bw   = brem - bh * HW;
    const size_t bimg = (size_t)bn * PIX;

    // ---- async stage issue ----
    auto issue = [&](int kt) {
        const int st = kt % 3;
        // A: weights [kt][mBase..mBase+127][64], 1024 uint4 per part
#pragma unroll
        for (int part = 0; part < 2; ++part) {
            const uint4* wsrc = (const uint4*)(part ? g_w_lo : g_w_hi) +
                                (size_t)(kt * 256 + mBase) * 8;
#pragma unroll
            for (int j = 0; j < 4; ++j) {
                int i = j * 256 + tid;
                int m = i >> 3, cb = i & 7;
                uint32_t dst = sbase + A_OFF(st, part) + sw128((uint32_t)(m * 128 + cb * 16));
                cp16(dst, wsrc + i, 16);
            }
        }
        // B: im2col rows, zero-fill out-of-bounds via src_size = 0
        const int rs = kt >> 1, chalf = kt & 1;
        const int r = rs / 3, s = rs - r * 3;
        const int ih = bh + r - 1, iw = bw + s - 1;
        const bool valid = ((unsigned)ih < (unsigned)HW) && ((unsigned)iw < (unsigned)HW);
        const size_t eb = valid ? ((bimg + (size_t)ih * HW + iw) * C_IN + chalf * 64 + bhr * 32)
                                : 0;
        const int ssz = valid ? 16 : 0;
#pragma unroll
        for (int part = 0; part < 2; ++part) {
            const uint4* bsrc = (const uint4*)((part ? g_xt_lo : g_xt_hi) + eb);
#pragma unroll
            for (int j = 0; j < 4; ++j) {
                uint32_t dst = sbase + B_OFF(st, part) +
                               sw128((uint32_t)(brow * 128 + bhr * 64 + j * 16));
                cp16(dst, bsrc + j, ssz);
            }
        }
        asm volatile("cp.async.commit_group;" ::: "memory");
    };

    float acc[4][4][4];
#pragma unroll
    for (int i = 0; i < 4; ++i)
#pragma unroll
        for (int j = 0; j < 4; ++j)
#pragma unroll
            for (int q = 0; q < 4; ++q)
                acc[i][j][q] = 0.0f;

    issue(0);
    issue(1);

    // fragment lane addressing (ldmatrix x4 canonical)
    const int a_m      = wy * 64 + (l & 15);
    const uint32_t a_kb = (uint32_t)(l >> 4) * 16;
    const int b_n      = wx * 32 + (l & 7) + ((l >> 4) << 3);
    const uint32_t b_kb = (uint32_t)((l >> 3) & 1) * 16;

    for (int kt = 0; kt < NKT; ++kt) {
        const int st = kt % 3;
        if (kt == NKT - 1) asm volatile("cp.async.wait_group 0;" ::: "memory");
        else               asm volatile("cp.async.wait_group 1;" ::: "memory");
        __syncthreads();

        const uint32_t aB0 = sbase + A_OFF(st, 0), aB1 = sbase + A_OFF(st, 1);
        const uint32_t bB0 = sbase + B_OFF(st, 0), bB1 = sbase + B_OFF(st, 1);

#pragma unroll
        for (int k16 = 0; k16 < 4; ++k16) {
            uint32_t ah[4][4], al[4][4], bhf[2][4], blf[2][4];
#pragma unroll
            for (int mt = 0; mt < 4; ++mt) {
                uint32_t off = sw128((uint32_t)((a_m + mt * 16) * 128) + k16 * 32 + a_kb);
                ldsm4(ah[mt], aB0 + off);
                ldsm4(al[mt], aB1 + off);
            }
#pragma unroll
            for (int np = 0; np < 2; ++np) {
                uint32_t off = sw128((uint32_t)((b_n + np * 16) * 128) + k16 * 32 + b_kb);
                ldsm4(bhf[np], bB0 + off);
                ldsm4(blf[np], bB1 + off);
            }
#pragma unroll
            for (int mt = 0; mt < 4; ++mt) {
#pragma unroll
                for (int nt = 0; nt < 4; ++nt) {
                    const uint32_t* ph = &bhf[nt >> 1][(nt & 1) * 2];
                    const uint32_t* pl = &blf[nt >> 1][(nt & 1) * 2];
                    mma_bf16(acc[mt][nt], ah[mt], ph);   // hh
                    mma_bf16(acc[mt][nt], ah[mt], pl);   // hl
                    mma_bf16(acc[mt][nt], al[mt], ph);   // lh
                }
            }
        }
        __syncthreads();
        if (kt + 2 < NKT) issue(kt + 2);
    }

    // ---- epilogue: C frag -> NCHW out (+bias). 8-pixel groups stay in-image (8|3136). ----
#pragma unroll
    for (int mt = 0; mt < 4; ++mt) {
        const int ch0 = mBase + wy * 64 + mt * 16 + (l >> 2);
        const float bv0 = __ldg(&bias[ch0]);
        const float bv1 = __ldg(&bias[ch0 + 8]);
#pragma unroll
        for (int nt = 0; nt < 4; ++nt) {
            const int p0  = pixBase + wx * 32 + nt * 8 + (l & 3) * 2;
            const int on  = p0 / PIX;
            const int pin = p0 - on * PIX;
            float* o = out + ((size_t)on * K_OUT + ch0) * PIX + pin;
            float2 v0, v1;
            v0.x = acc[mt][nt][0] + bv0; v0.y = acc[mt][nt][1] + bv0;
            v1.x = acc[mt][nt][2] + bv1; v1.y = acc[mt][nt][3] + bv1;
            *(float2*)o             = v0;
            *(float2*)(o + 8 * PIX) = v1;
        }
    }
}

// ---------------- launch ----------------
extern "C" void kernel_launch(void* const* d_in, const int* in_sizes, int n_in,
                              void* d_out, int out_size) {
    const float* x    = (const float*)d_in[0];
    const float* wgt  = (const float*)d_in[1];
    const float* bias = (const float*)d_in[2];
    float* out        = (float*)d_out;

    cudaFuncSetAttribute(conv_mma_kernel,
                         cudaFuncAttributeMaxDynamicSharedMemorySize, SMEM_TOTAL);

    wprep_kernel<<<(256 * 1152) / 256, 256>>>(wgt);
    {
        dim3 g(PIX / 32, C_IN / 32, N_IMG);   // (98, 4, 32)
        dim3 b(32, 8);
        xprep_kernel<<<g, b>>>(x);
    }
    conv_mma_kernel<<<dim3(NPIX / BN, K_OUT / BM), NTHREADS, SMEM_TOTAL>>>(bias, out);
}

// round 5
// speedup vs baseline: 5.4835x; 1.7496x over previous
#include <cuda_runtime.h>
#include <cuda_fp16.h>
#include <stdint.h>

// Conv 3x3 s1 p1, NCHW fp32: x[32,128,56,56] * w[256,128,3,3] + bias -> out[32,256,56,56]
// fp16 implicit GEMM on mma.sync.m16n8k16 (fp32 accum). Norm rel_err ~2e-4 (<1e-3).

#define N_IMG 32
#define C_IN  128
#define HW    56
#define PIX   3136              // 56*56
#define K_OUT 256
#define NPIX  100352            // 32*3136
#define BM    128               // out-channels per CTA
#define BN    256               // pixels per CTA
#define NKT   18                // K steps: 9 (r,s) x 2 c-halves of 64
#define NTHREADS 256

// ---------------- scratch (device globals; no allocs allowed) ----------------
__device__ __align__(16) __half g_xt[(size_t)NPIX * C_IN];   // NHWC fp16
__device__ __align__(16) __half g_w[NKT * 256 * 64];         // [kt][m][c64] fp16

// ---------------- helpers ----------------
__device__ __forceinline__ uint32_t smem_u32(const void* p) {
    uint32_t a;
    asm("{ .reg .u64 t; cvta.to.shared.u64 t, %1; cvt.u32.u64 %0, t; }" : "=r"(a) : "l"(p));
    return a;
}
__device__ __forceinline__ uint32_t sw128(uint32_t off) { return off ^ ((off >> 3) & 0x70); }

__device__ __forceinline__ void cp16(uint32_t dst, const void* src, int src_sz) {
    asm volatile("cp.async.cg.shared.global [%0], [%1], 16, %2;"
                 :: "r"(dst), "l"(src), "r"(src_sz) : "memory");
}
__device__ __forceinline__ void ldsm4(uint32_t* r, uint32_t a) {
    asm volatile("ldmatrix.sync.aligned.m8n8.x4.shared.b16 {%0,%1,%2,%3}, [%4];"
                 : "=r"(r[0]), "=r"(r[1]), "=r"(r[2]), "=r"(r[3]) : "r"(a));
}
__device__ __forceinline__ void mma_fp16(float* c, const uint32_t* a, const uint32_t* b) {
    asm volatile(
        "mma.sync.aligned.m16n8k16.row.col.f32.f16.f16.f32 "
        "{%0,%1,%2,%3}, {%4,%5,%6,%7}, {%8,%9}, {%0,%1,%2,%3};"
        : "+f"(c[0]), "+f"(c[1]), "+f"(c[2]), "+f"(c[3])
        : "r"(a[0]), "r"(a[1]), "r"(a[2]), "r"(a[3]), "r"(b[0]), "r"(b[1]));
}

// ---------------- smem: 4-stage ring, 48 KB/stage: A 16K | B 32K ----------------
#define STAGE_BYTES 49152
#define A_OFF(st) ((st) * STAGE_BYTES)
#define B_OFF(st) ((st) * STAGE_BYTES + 16384)
#define SMEM_TOTAL (4 * STAGE_BYTES)

// ---------------- prep kernels ----------------
__global__ void wprep_kernel(const float* __restrict__ w) {
    int idx = blockIdx.x * 256 + threadIdx.x;     // < 256*1152
    int m = idx / 1152;
    int k = idx - m * 1152;
    int c = k / 9;
    int rs = k - c * 9;
    int kt = rs * 2 + (c >> 6);
    g_w[(kt * 256 + m) * 64 + (c & 63)] = __float2half(w[idx]);
}

__global__ void xprep_kernel(const float* __restrict__ x) {
    __shared__ float t[32][33];
    const int n  = blockIdx.z;
    const int c0 = blockIdx.y * 32;
    const int p0 = blockIdx.x * 32;
    const int tx = threadIdx.x, ty = threadIdx.y;   // 32 x 8
    const float* src = x + ((size_t)n * C_IN + c0) * PIX + p0;
#pragma unroll
    for (int i = 0; i < 4; ++i) {
        int c = ty + i * 8;
        t[c][tx] = src[(size_t)c * PIX + tx];
    }
    __syncthreads();
#pragma unroll
    for (int i = 0; i < 4; ++i) {
        int pr = ty + i * 8;
        g_xt[((size_t)n * PIX + p0 + pr) * C_IN + c0 + tx] = __float2half(t[tx][pr]);
    }
}

// ---------------- main conv kernel ----------------
__global__ __launch_bounds__(NTHREADS, 1)
void conv_mma_fp16_kernel(const float* __restrict__ bias, float* __restrict__ out) {
    extern __shared__ char smem[];
    const uint32_t sbase = smem_u32(smem);
    const int tid = threadIdx.x;
    const int wid = tid >> 5;
    const int l   = tid & 31;
    const int pixBase = blockIdx.x * BN;
    const int mBase   = blockIdx.y * BM;
    const int wy = wid & 1;            // M half (64 rows)
    const int wx = wid >> 1;           // N quarter (64 pixels)

    // ---- per-thread B-row geometry: thread tid owns pixel row tid ----
    const int p    = pixBase + tid;
    const int bn   = p / PIX;
    const int brem = p - bn * PIX;
    const int bh   = brem / HW;
    const int bw   = brem - bh * HW;
    const size_t bimg = (size_t)bn * PIX;

    // ---- async stage issue ----
    auto issue = [&](int kt) {
        const int st = kt & 3;
        // A: weights [kt][mBase..mBase+127][64] -> 1024 uint4
        const uint4* wsrc = (const uint4*)g_w + (size_t)(kt * 256 + mBase) * 8;
#pragma unroll
        for (int j = 0; j < 4; ++j) {
            int i = j * 256 + tid;
            uint32_t dst = sbase + A_OFF(st) + sw128((uint32_t)((i >> 3) * 128 + (i & 7) * 16));
            cp16(dst, wsrc + i, 16);
        }
        // B: im2col row (64 ch = 128B = 8 uint4); zero-fill OOB via src_size = 0
        const int rs = kt >> 1, chalf = kt & 1;
        const int r = rs / 3, s = rs - r * 3;
        const int ih = bh + r - 1, iw = bw + s - 1;
        const bool valid = ((unsigned)ih < (unsigned)HW) && ((unsigned)iw < (unsigned)HW);
        const size_t eb = valid ? ((bimg + (size_t)ih * HW + iw) * C_IN + chalf * 64) : 0;
        const int ssz = valid ? 16 : 0;
        const uint4* bsrc = (const uint4*)(g_xt + eb);
#pragma unroll
        for (int j = 0; j < 8; ++j) {
            uint32_t dst = sbase + B_OFF(st) + sw128((uint32_t)(tid * 128 + j * 16));
            cp16(dst, bsrc + j, ssz);
        }
        asm volatile("cp.async.commit_group;" ::: "memory");
    };

    float acc[4][8][4];
#pragma unroll
    for (int i = 0; i < 4; ++i)
#pragma unroll
        for (int j = 0; j < 8; ++j)
#pragma unroll
            for (int q = 0; q < 4; ++q)
                acc[i][j][q] = 0.0f;

    issue(0);
    issue(1);
    issue(2);

    // fragment lane addressing (ldmatrix x4 canonical, validated in round 4)
    const int a_m       = wy * 64 + (l & 15);
    const uint32_t a_kb = (uint32_t)(l >> 4) * 16;
    const int b_n       = wx * 64 + (l & 7) + ((l >> 4) << 3);
    const uint32_t b_kb = (uint32_t)((l >> 3) & 1) * 16;

    for (int kt = 0; kt < NKT; ++kt) {
        const int st = kt & 3;
        const int rem = NKT - 1 - kt;
        if (rem >= 2)      asm volatile("cp.async.wait_group 2;" ::: "memory");
        else if (rem == 1) asm volatile("cp.async.wait_group 1;" ::: "memory");
        else               asm volatile("cp.async.wait_group 0;" ::: "memory");
        __syncthreads();
        if (kt + 3 < NKT) issue(kt + 3);   // overlaps with compute below

        const uint32_t aB = sbase + A_OFF(st);
        const uint32_t bB = sbase + B_OFF(st);

#pragma unroll
        for (int k16 = 0; k16 < 4; ++k16) {
            uint32_t af[4][4], bf[4][4];
#pragma unroll
            for (int mt = 0; mt < 4; ++mt)
                ldsm4(af[mt], aB + sw128((uint32_t)((a_m + mt * 16) * 128) + k16 * 32 + a_kb));
#pragma unroll
            for (int np = 0; np < 4; ++np)
                ldsm4(bf[np], bB + sw128((uint32_t)((b_n + np * 16) * 128) + k16 * 32 + b_kb));
#pragma unroll
            for (int mt = 0; mt < 4; ++mt)
#pragma unroll
                for (int nt = 0; nt < 8; ++nt)
                    mma_fp16(acc[mt][nt], af[mt], &bf[nt >> 1][(nt & 1) * 2]);
        }
    }

    // ---- epilogue: C frag -> NCHW out (+bias). 8-pixel groups stay in-image. ----
#pragma unroll
    for (int mt = 0; mt < 4; ++mt) {
        const int ch0 = mBase + wy * 64 + mt * 16 + (l >> 2);
        const float bv0 = __ldg(&bias[ch0]);
        const float bv1 = __ldg(&bias[ch0 + 8]);
#pragma unroll
        for (int nt = 0; nt < 8; ++nt) {
            const int p0  = pixBase + wx * 64 + nt * 8 + (l & 3) * 2;
            const int on  = p0 / PIX;
            const int pin = p0 - on * PIX;
            float* o = out + ((size_t)on * K_OUT + ch0) * PIX + pin;
            float2 v0, v1;
            v0.x = acc[mt][nt][0] + bv0; v0.y = acc[mt][nt][1] + bv0;
            v1.x = acc[mt][nt][2] + bv1; v1.y = acc[mt][nt][3] + bv1;
            *(float2*)o             = v0;
            *(float2*)(o + 8 * PIX) = v1;
        }
    }
}

// ---------------- launch ----------------
extern "C" void kernel_launch(void* const* d_in, const int* in_sizes, int n_in,
                              void* d_out, int out_size) {
    const float* x    = (const float*)d_in[0];
    const float* wgt  = (const float*)d_in[1];
    const float* bias = (const float*)d_in[2];
    float* out        = (float*)d_out;

    cudaFuncSetAttribute(conv_mma_fp16_kernel,
                         cudaFuncAttributeMaxDynamicSharedMemorySize, SMEM_TOTAL);

    wprep_kernel<<<(256 * 1152) / 256, 256>>>(wgt);
    {
        dim3 g(PIX / 32, C_IN / 32, N_IMG);   // (98, 4, 32)
        dim3 b(32, 8);
        xprep_kernel<<<g, b>>>(x);
    }
    conv_mma_fp16_kernel<<<dim3(NPIX / BN, K_OUT / BM), NTHREADS, SMEM_TOTAL>>>(bias, out);
}

// round 6
// speedup vs baseline: 5.5076x; 1.0044x over previous
#include <cuda_runtime.h>
#include <cuda_fp16.h>
#include <stdint.h>

// Conv 3x3 s1 p1, NCHW fp32: x[32,128,56,56] * w[256,128,3,3] + bias -> out[32,256,56,56]
// fp16 implicit GEMM on mma.sync.m16n8k16 (fp32 accum), double-buffered ldmatrix frags.

#define N_IMG 32
#define C_IN  128
#define HW    56
#define PIX   3136              // 56*56
#define K_OUT 256
#define NPIX  100352            // 32*3136
#define BM    128               // out-channels per CTA
#define BN    256               // pixels per CTA
#define NKT   18                // K steps: 9 (r,s) x 2 c-halves of 64
#define NTHREADS 256

// ---------------- scratch (device globals; no allocs allowed) ----------------
__device__ __align__(16) __half g_xt[(size_t)NPIX * C_IN];   // NHWC fp16
__device__ __align__(16) __half g_w[NKT * 256 * 64];         // [kt][m][c64] fp16

// ---------------- helpers ----------------
__device__ __forceinline__ uint32_t smem_u32(const void* p) {
    uint32_t a;
    asm("{ .reg .u64 t; cvta.to.shared.u64 t, %1; cvt.u32.u64 %0, t; }" : "=r"(a) : "l"(p));
    return a;
}
__device__ __forceinline__ uint32_t sw128(uint32_t off) { return off ^ ((off >> 3) & 0x70); }

__device__ __forceinline__ void cp16(uint32_t dst, const void* src, int src_sz) {
    asm volatile("cp.async.cg.shared.global [%0], [%1], 16, %2;"
                 :: "r"(dst), "l"(src), "r"(src_sz) : "memory");
}
__device__ __forceinline__ void ldsm4(uint32_t* r, uint32_t a) {
    asm volatile("ldmatrix.sync.aligned.m8n8.x4.shared.b16 {%0,%1,%2,%3}, [%4];"
                 : "=r"(r[0]), "=r"(r[1]), "=r"(r[2]), "=r"(r[3]) : "r"(a));
}
__device__ __forceinline__ void mma_fp16(float* c, const uint32_t* a, const uint32_t* b) {
    asm volatile(
        "mma.sync.aligned.m16n8k16.row.col.f32.f16.f16.f32 "
        "{%0,%1,%2,%3}, {%4,%5,%6,%7}, {%8,%9}, {%0,%1,%2,%3};"
        : "+f"(c[0]), "+f"(c[1]), "+f"(c[2]), "+f"(c[3])
        : "r"(a[0]), "r"(a[1]), "r"(a[2]), "r"(a[3]), "r"(b[0]), "r"(b[1]));
}

// ---------------- smem: 4-stage ring, 48 KB/stage: A 16K | B 32K ----------------
#define STAGE_BYTES 49152
#define A_OFF(st) ((st) * STAGE_BYTES)
#define B_OFF(st) ((st) * STAGE_BYTES + 16384)
#define SMEM_TOTAL (4 * STAGE_BYTES)

// ---------------- prep kernels ----------------
__global__ void wprep_kernel(const float* __restrict__ w) {
    int idx = blockIdx.x * 256 + threadIdx.x;     // < 256*1152
    int m = idx / 1152;
    int k = idx - m * 1152;
    int c = k / 9;
    int rs = k - c * 9;
    int kt = rs * 2 + (c >> 6);
    g_w[(kt * 256 + m) * 64 + (c & 63)] = __float2half(w[idx]);
}

__global__ void xprep_kernel(const float* __restrict__ x) {
    __shared__ float t[32][33];
    const int n  = blockIdx.z;
    const int c0 = blockIdx.y * 32;
    const int p0 = blockIdx.x * 32;
    const int tx = threadIdx.x, ty = threadIdx.y;   // 32 x 8
    const float* src = x + ((size_t)n * C_IN + c0) * PIX + p0;
#pragma unroll
    for (int i = 0; i < 4; ++i) {
        int c = ty + i * 8;
        t[c][tx] = src[(size_t)c * PIX + tx];
    }
    __syncthreads();
#pragma unroll
    for (int i = 0; i < 4; ++i) {
        int pr = ty + i * 8;
        g_xt[((size_t)n * PIX + p0 + pr) * C_IN + c0 + tx] = __float2half(t[tx][pr]);
    }
}

// ---------------- main conv kernel ----------------
__global__ __launch_bounds__(NTHREADS, 1)
void conv_mma_fp16_kernel(const float* __restrict__ bias, float* __restrict__ out) {
    extern __shared__ char smem[];
    const uint32_t sbase = smem_u32(smem);
    const int tid = threadIdx.x;
    const int wid = tid >> 5;
    const int l   = tid & 31;
    const int pixBase = blockIdx.x * BN;
    const int mBase   = blockIdx.y * BM;
    const int wy = wid & 1;            // M half (64 rows)
    const int wx = wid >> 1;           // N quarter (64 pixels)

    // ---- per-thread B-row geometry: thread tid owns pixel row tid ----
    const int p    = pixBase + tid;
    const int bn   = p / PIX;
    const int brem = p - bn * PIX;
    const int bh   = brem / HW;
    const int bw   = brem - bh * HW;
    const size_t bimg = (size_t)bn * PIX;

    // ---- async stage issue ----
    auto issue = [&](int kt) {
        const int st = kt & 3;
        // A: weights [kt][mBase..mBase+127][64] -> 1024 uint4
        const uint4* wsrc = (const uint4*)g_w + (size_t)(kt * 256 + mBase) * 8;
#pragma unroll
        for (int j = 0; j < 4; ++j) {
            int i = j * 256 + tid;
            uint32_t dst = sbase + A_OFF(st) + sw128((uint32_t)((i >> 3) * 128 + (i & 7) * 16));
            cp16(dst, wsrc + i, 16);
        }
        // B: im2col row (64 ch = 128B = 8 uint4); zero-fill OOB via src_size = 0
        const int rs = kt >> 1, chalf = kt & 1;
        const int r = rs / 3, s = rs - r * 3;
        const int ih = bh + r - 1, iw = bw + s - 1;
        const bool valid = ((unsigned)ih < (unsigned)HW) && ((unsigned)iw < (unsigned)HW);
        const size_t eb = valid ? ((bimg + (size_t)ih * HW + iw) * C_IN + chalf * 64) : 0;
        const int ssz = valid ? 16 : 0;
        const uint4* bsrc = (const uint4*)(g_xt + eb);
#pragma unroll
        for (int j = 0; j < 8; ++j) {
            uint32_t dst = sbase + B_OFF(st) + sw128((uint32_t)(tid * 128 + j * 16));
            cp16(dst, bsrc + j, ssz);
        }
        asm volatile("cp.async.commit_group;" ::: "memory");
    };

    float acc[4][8][4];
#pragma unroll
    for (int i = 0; i < 4; ++i)
#pragma unroll
        for (int j = 0; j < 8; ++j)
#pragma unroll
            for (int q = 0; q < 4; ++q)
                acc[i][j][q] = 0.0f;

    issue(0);
    issue(1);
    issue(2);

    // fragment lane addressing (ldmatrix x4 canonical, validated)
    const int a_m       = wy * 64 + (l & 15);
    const uint32_t a_kb = (uint32_t)(l >> 4) * 16;
    const int b_n       = wx * 64 + (l & 7) + ((l >> 4) << 3);
    const uint32_t b_kb = (uint32_t)((l >> 3) & 1) * 16;

    // double-buffered fragments
    uint32_t af[2][4][4], bf[2][4][4];

    for (int kt = 0; kt < NKT; ++kt) {
        const int st = kt & 3;
        const int rem = NKT - 1 - kt;
        if (rem >= 2)      asm volatile("cp.async.wait_group 2;" ::: "memory");
        else if (rem == 1) asm volatile("cp.async.wait_group 1;" ::: "memory");
        else               asm volatile("cp.async.wait_group 0;" ::: "memory");
        __syncthreads();
        if (kt + 3 < NKT) issue(kt + 3);   // overlaps with compute below

        const uint32_t aB = sbase + A_OFF(st);
        const uint32_t bB = sbase + B_OFF(st);

        // prologue frag load for k16=0
#pragma unroll
        for (int mt = 0; mt < 4; ++mt)
            ldsm4(af[0][mt], aB + sw128((uint32_t)((a_m + mt * 16) * 128) + a_kb));
#pragma unroll
        for (int np = 0; np < 4; ++np)
            ldsm4(bf[0][np], bB + sw128((uint32_t)((b_n + np * 16) * 128) + b_kb));

#pragma unroll
        for (int k16 = 0; k16 < 4; ++k16) {
            const int cur = k16 & 1;
            if (k16 < 3) {
                const int nxt = cur ^ 1;
                const uint32_t kb = (uint32_t)(k16 + 1) * 32;
#pragma unroll
                for (int mt = 0; mt < 4; ++mt)
                    ldsm4(af[nxt][mt],
                          aB + sw128((uint32_t)((a_m + mt * 16) * 128) + kb + a_kb));
#pragma unroll
                for (int np = 0; np < 4; ++np)
                    ldsm4(bf[nxt][np],
                          bB + sw128((uint32_t)((b_n + np * 16) * 128) + kb + b_kb));
            }
#pragma unroll
            for (int mt = 0; mt < 4; ++mt)
#pragma unroll
                for (int nt = 0; nt < 8; ++nt)
                    mma_fp16(acc[mt][nt], af[cur][mt], &bf[cur][nt >> 1][(nt & 1) * 2]);
        }
    }

    // ---- epilogue: C frag -> NCHW out (+bias). 8-pixel groups stay in-image. ----
#pragma unroll
    for (int mt = 0; mt < 4; ++mt) {
        const int ch0 = mBase + wy * 64 + mt * 16 + (l >> 2);
        const float bv0 = __ldg(&bias[ch0]);
        const float bv1 = __ldg(&bias[ch0 + 8]);
#pragma unroll
        for (int nt = 0; nt < 8; ++nt) {
            const int p0  = pixBase + wx * 64 + nt * 8 + (l & 3) * 2;
            const int on  = p0 / PIX;
            const int pin = p0 - on * PIX;
            float* o = out + ((size_t)on * K_OUT + ch0) * PIX + pin;
            float2 v0, v1;
            v0.x = acc[mt][nt][0] + bv0; v0.y = acc[mt][nt][1] + bv0;
            v1.x = acc[mt][nt][2] + bv1; v1.y = acc[mt][nt][3] + bv1;
            *(float2*)o             = v0;
            *(float2*)(o + 8 * PIX) = v1;
        }
    }
}

// ---------------- launch ----------------
extern "C" void kernel_launch(void* const* d_in, const int* in_sizes, int n_in,
                              void* d_out, int out_size) {
    const float* x    = (const float*)d_in[0];
    const float* wgt  = (const float*)d_in[1];
    const float* bias = (const float*)d_in[2];
    float* out        = (float*)d_out;

    cudaFuncSetAttribute(conv_mma_fp16_kernel,
                         cudaFuncAttributeMaxDynamicSharedMemorySize, SMEM_TOTAL);

    wprep_kernel<<<(256 * 1152) / 256, 256>>>(wgt);
    {
        dim3 g(PIX / 32, C_IN / 32, N_IMG);   // (98, 4, 32)
        dim3 b(32, 8);
        xprep_kernel<<<g, b>>>(x);
    }
    conv_mma_fp16_kernel<<<dim3(NPIX / BN, K_OUT / BM), NTHREADS, SMEM_TOTAL>>>(bias, out);
}

// round 7
// speedup vs baseline: 8.0525x; 1.4621x over previous
#include <cuda_runtime.h>
#include <cuda_fp16.h>
#include <stdint.h>

// Conv 3x3 s1 p1, NCHW fp32: x[32,128,56,56] * w[256,128,3,3] + bias -> out[32,256,56,56]
// fp16 implicit GEMM on mma.sync.m16n8k16 (fp32 accum). Occupancy-2 variant:
// BM=BN=128, warp tile 64x32, 3-stage x 32KB ring, <=128 regs/thread.

#define N_IMG 32
#define C_IN  128
#define HW    56
#define PIX   3136              // 56*56
#define K_OUT 256
#define NPIX  100352            // 32*3136
#define BM    128               // out-channels per CTA
#define BN    128               // pixels per CTA
#define NKT   18                // K steps: 9 (r,s) x 2 c-halves of 64
#define NTHREADS 256

// ---------------- scratch (device globals; no allocs allowed) ----------------
__device__ __align__(16) __half g_xt[(size_t)NPIX * C_IN];   // NHWC fp16
__device__ __align__(16) __half g_w[NKT * 256 * 64];         // [kt][m][c64] fp16

// ---------------- helpers ----------------
__device__ __forceinline__ uint32_t smem_u32(const void* p) {
    uint32_t a;
    asm("{ .reg .u64 t; cvta.to.shared.u64 t, %1; cvt.u32.u64 %0, t; }" : "=r"(a) : "l"(p));
    return a;
}
__device__ __forceinline__ uint32_t sw128(uint32_t off) { return off ^ ((off >> 3) & 0x70); }

__device__ __forceinline__ void cp16(uint32_t dst, const void* src, int src_sz) {
    asm volatile("cp.async.cg.shared.global [%0], [%1], 16, %2;"
                 :: "r"(dst), "l"(src), "r"(src_sz) : "memory");
}
__device__ __forceinline__ void ldsm4(uint32_t* r, uint32_t a) {
    asm volatile("ldmatrix.sync.aligned.m8n8.x4.shared.b16 {%0,%1,%2,%3}, [%4];"
                 : "=r"(r[0]), "=r"(r[1]), "=r"(r[2]), "=r"(r[3]) : "r"(a));
}
__device__ __forceinline__ void mma_fp16(float* c, const uint32_t* a, const uint32_t* b) {
    asm volatile(
        "mma.sync.aligned.m16n8k16.row.col.f32.f16.f16.f32 "
        "{%0,%1,%2,%3}, {%4,%5,%6,%7}, {%8,%9}, {%0,%1,%2,%3};"
        : "+f"(c[0]), "+f"(c[1]), "+f"(c[2]), "+f"(c[3])
        : "r"(a[0]), "r"(a[1]), "r"(a[2]), "r"(a[3]), "r"(b[0]), "r"(b[1]));
}

// ---------------- smem: 3-stage ring, 32 KB/stage: A 16K | B 16K ----------------
#define STAGE_BYTES 32768
#define A_OFF(st) ((st) * STAGE_BYTES)
#define B_OFF(st) ((st) * STAGE_BYTES + 16384)
#define SMEM_TOTAL (3 * STAGE_BYTES)

// ---------------- prep kernels ----------------
__global__ void wprep_kernel(const float* __restrict__ w) {
    int idx = blockIdx.x * 256 + threadIdx.x;     // < 256*1152
    int m = idx / 1152;
    int k = idx - m * 1152;
    int c = k / 9;
    int rs = k - c * 9;
    int kt = rs * 2 + (c >> 6);
    g_w[(kt * 256 + m) * 64 + (c & 63)] = __float2half(w[idx]);
}

__global__ void xprep_kernel(const float* __restrict__ x) {
    __shared__ float t[32][33];
    const int n  = blockIdx.z;
    const int c0 = blockIdx.y * 32;
    const int p0 = blockIdx.x * 32;
    const int tx = threadIdx.x, ty = threadIdx.y;   // 32 x 8
    const float* src = x + ((size_t)n * C_IN + c0) * PIX + p0;
#pragma unroll
    for (int i = 0; i < 4; ++i) {
        int c = ty + i * 8;
        t[c][tx] = src[(size_t)c * PIX + tx];
    }
    __syncthreads();
#pragma unroll
    for (int i = 0; i < 4; ++i) {
        int pr = ty + i * 8;
        g_xt[((size_t)n * PIX + p0 + pr) * C_IN + c0 + tx] = __float2half(t[tx][pr]);
    }
}

// ---------------- main conv kernel ----------------
__global__ __launch_bounds__(NTHREADS, 2)
void conv_mma_fp16_kernel(const float* __restrict__ bias, float* __restrict__ out) {
    extern __shared__ char smem[];
    const uint32_t sbase = smem_u32(smem);
    const int tid = threadIdx.x;
    const int wid = tid >> 5;
    const int l   = tid & 31;
    const int pixBase = blockIdx.x * BN;
    const int mBase   = blockIdx.y * BM;
    const int wy = wid & 1;            // M half (64 rows)
    const int wx = wid >> 1;           // N quarter (32 pixels)

    // ---- per-thread B-row geometry: thread pair owns pixel row tid>>1 ----
    const int brow = tid >> 1;          // 0..127
    const int bhr  = tid & 1;           // half-row (64B)
    const int p    = pixBase + brow;
    const int bn   = p / PIX;
    const int brem = p - bn * PIX;
    const int bh   = brem / HW;
    const int bw   = brem - bh * HW;
    const size_t bimg = (size_t)bn * PIX;

    // ---- async stage issue ----
    auto issue = [&](int kt) {
        const int st = kt % 3;
        // A: weights [kt][mBase..mBase+127][64] = 16KB -> 1024 uint4
        const uint4* wsrc = (const uint4*)g_w + (size_t)(kt * 256 + mBase) * 8;
#pragma unroll
        for (int j = 0; j < 4; ++j) {
            int i = j * 256 + tid;
            uint32_t dst = sbase + A_OFF(st) + sw128((uint32_t)((i >> 3) * 128 + (i & 7) * 16));
            cp16(dst, wsrc + i, 16);
        }
        // B: im2col row (64 ch = 128B); thread pair covers one row, zero-fill OOB
        const int rs = kt >> 1, chalf = kt & 1;
        const int r = rs / 3, s = rs - r * 3;
        const int ih = bh + r - 1, iw = bw + s - 1;
        const bool valid = ((unsigned)ih < (unsigned)HW) && ((unsigned)iw < (unsigned)HW);
        const size_t eb = valid ? ((bimg + (size_t)ih * HW + iw) * C_IN + chalf * 64 + bhr * 32)
                                : 0;
        const int ssz = valid ? 16 : 0;
        const uint4* bsrc = (const uint4*)(g_xt + eb);
#pragma unroll
        for (int j = 0; j < 4; ++j) {
            uint32_t dst = sbase + B_OFF(st) +
                           sw128((uint32_t)(brow * 128 + bhr * 64 + j * 16));
            cp16(dst, bsrc + j, ssz);
        }
        asm volatile("cp.async.commit_group;" ::: "memory");
    };

    float acc[4][4][4];
#pragma unroll
    for (int i = 0; i < 4; ++i)
#pragma unroll
        for (int j = 0; j < 4; ++j)
#pragma unroll
            for (int q = 0; q < 4; ++q)
                acc[i][j][q] = 0.0f;

    issue(0);
    issue(1);

    // fragment lane addressing (ldmatrix x4 canonical, validated)
    const int a_m       = wy * 64 + (l & 15);
    const uint32_t a_kb = (uint32_t)(l >> 4) * 16;
    const int b_n       = wx * 32 + (l & 7) + ((l >> 4) << 3);
    const uint32_t b_kb = (uint32_t)((l >> 3) & 1) * 16;

    for (int kt = 0; kt < NKT; ++kt) {
        const int st = kt % 3;
        if (kt == NKT - 1) asm volatile("cp.async.wait_group 0;" ::: "memory");
        else               asm volatile("cp.async.wait_group 1;" ::: "memory");
        __syncthreads();
        if (kt + 2 < NKT) issue(kt + 2);   // overlaps with compute below

        const uint32_t aB = sbase + A_OFF(st);
        const uint32_t bB = sbase + B_OFF(st);

#pragma unroll
        for (int k16 = 0; k16 < 4; ++k16) {
            uint32_t af[4][4], bf[2][4];
            const uint32_t kb = (uint32_t)k16 * 32;
#pragma unroll
            for (int mt = 0; mt < 4; ++mt)
                ldsm4(af[mt], aB + sw128((uint32_t)((a_m + mt * 16) * 128) + kb + a_kb));
#pragma unroll
            for (int np = 0; np < 2; ++np)
                ldsm4(bf[np], bB + sw128((uint32_t)((b_n + np * 16) * 128) + kb + b_kb));
#pragma unroll
            for (int mt = 0; mt < 4; ++mt)
#pragma unroll
                for (int nt = 0; nt < 4; ++nt)
                    mma_fp16(acc[mt][nt], af[mt], &bf[nt >> 1][(nt & 1) * 2]);
        }
        __syncthreads();
    }

    // ---- epilogue: C frag -> NCHW out (+bias). 8-pixel groups stay in-image. ----
#pragma unroll
    for (int mt = 0; mt < 4; ++mt) {
        const int ch0 = mBase + wy * 64 + mt * 16 + (l >> 2);
        const float bv0 = __ldg(&bias[ch0]);
        const float bv1 = __ldg(&bias[ch0 + 8]);
#pragma unroll
        for (int nt = 0; nt < 4; ++nt) {
            const int p0  = pixBase + wx * 32 + nt * 8 + (l & 3) * 2;
            const int on  = p0 / PIX;
            const int pin = p0 - on * PIX;
            float* o = out + ((size_t)on * K_OUT + ch0) * PIX + pin;
            float2 v0, v1;
            v0.x = acc[mt][nt][0] + bv0; v0.y = acc[mt][nt][1] + bv0;
            v1.x = acc[mt][nt][2] + bv1; v1.y = acc[mt][nt][3] + bv1;
            *(float2*)o             = v0;
            *(float2*)(o + 8 * PIX) = v1;
        }
    }
}

// ---------------- launch ----------------
extern "C" void kernel_launch(void* const* d_in, const int* in_sizes, int n_in,
                              void* d_out, int out_size) {
    const float* x    = (const float*)d_in[0];
    const float* wgt  = (const float*)d_in[1];
    const float* bias = (const float*)d_in[2];
    float* out        = (float*)d_out;

    cudaFuncSetAttribute(conv_mma_fp16_kernel,
                         cudaFuncAttributeMaxDynamicSharedMemorySize, SMEM_TOTAL);

    wprep_kernel<<<(256 * 1152) / 256, 256>>>(wgt);
    {
        dim3 g(PIX / 32, C_IN / 32, N_IMG);   // (98, 4, 32)
        dim3 b(32, 8);
        xprep_kernel<<<g, b>>>(x);
    }
    conv_mma_fp16_kernel<<<dim3(NPIX / BN, K_OUT / BM), NTHREADS, SMEM_TOTAL>>>(bias, out);
}